// round 1
// baseline (speedup 1.0000x reference)
#include <cuda_runtime.h>
#include <math.h>

#define BSZ   16
#define SEQ   4096
#define NST   256
#define HIN   128
#define HOUT  128
#define MTOT  (BSZ*SEQ)      // 65536
#define CHUNK 128
#define NCH   (SEQ/CHUNK)    // 32

// Scratch (allocation-free: device globals). Bu_{re,im} are overwritten in
// place by the scan phase-3 with the shifted states pre_t = x_{t-1}.
__device__ float g_bu_re[(size_t)MTOT*NST];
__device__ float g_bu_im[(size_t)MTOT*NST];
__device__ float g_part_re[BSZ*NCH*NST];
__device__ float g_part_im[BSZ*NCH*NST];

__device__ __forceinline__ void lam_of(const float* __restrict__ nu_log,
                                       const float* __restrict__ th_log,
                                       int n, float& lr, float& li) {
    float mod = expf(-expf(nu_log[n]));
    float th  = expf(th_log[n]);
    lr = mod * cosf(th);
    li = mod * sinf(th);
}

// ---------------------------------------------------------------------------
// GEMM 1: Bu[m,n] = gamma[n] * sum_h u[m,h] * B[n,h]   (z=0: re, z=1: im)
// 64x64 tile, 256 threads, 4x4 microtile.
// ---------------------------------------------------------------------------
__global__ __launch_bounds__(256) void gemm_bu_kernel(
    const float* __restrict__ u, const float* __restrict__ Bre,
    const float* __restrict__ Bim, const float* __restrict__ gamma_log)
{
    __shared__ __align__(16) float As[32][68];
    __shared__ __align__(16) float Ws[32][68];
    const float* W  = blockIdx.z ? Bim : Bre;
    float* out      = blockIdx.z ? g_bu_im : g_bu_re;
    const int m0 = blockIdx.x * 64;
    const int n0 = blockIdx.y * 64;
    const int tid = threadIdx.x;
    const int tx = tid & 15, ty = tid >> 4;

    float acc[4][4] = {};

    for (int k0 = 0; k0 < HIN; k0 += 32) {
        #pragma unroll
        for (int i = 0; i < 8; i++) {
            int idx = tid + i * 256;
            int r = idx >> 5, kk = idx & 31;
            As[kk][r] = u[(size_t)(m0 + r) * HIN + (k0 + kk)];
            Ws[kk][r] = W[(size_t)(n0 + r) * HIN + (k0 + kk)];
        }
        __syncthreads();
        #pragma unroll
        for (int kk = 0; kk < 32; kk++) {
            float4 a4 = *reinterpret_cast<const float4*>(&As[kk][ty * 4]);
            float4 b4 = *reinterpret_cast<const float4*>(&Ws[kk][tx * 4]);
            float av[4] = {a4.x, a4.y, a4.z, a4.w};
            float bv[4] = {b4.x, b4.y, b4.z, b4.w};
            #pragma unroll
            for (int i = 0; i < 4; i++)
                #pragma unroll
                for (int j = 0; j < 4; j++)
                    acc[i][j] = fmaf(av[i], bv[j], acc[i][j]);
        }
        __syncthreads();
    }

    float g4[4];
    #pragma unroll
    for (int j = 0; j < 4; j++) g4[j] = expf(gamma_log[n0 + tx * 4 + j]);
    #pragma unroll
    for (int i = 0; i < 4; i++) {
        int m = m0 + ty * 4 + i;
        float4 v;
        v.x = acc[i][0] * g4[0];
        v.y = acc[i][1] * g4[1];
        v.z = acc[i][2] * g4[2];
        v.w = acc[i][3] * g4[3];
        *reinterpret_cast<float4*>(&out[(size_t)m * NST + n0 + tx * 4]) = v;
    }
}

// ---------------------------------------------------------------------------
// Scan phase 1: per-chunk reduce. One thread per (b, chunk, n).
// X_c = sum_{t in chunk} lam^{(chunk_end - t)} Bu_t  (i.e. chunk run from 0)
// ---------------------------------------------------------------------------
__global__ __launch_bounds__(NST) void scan_phase1(
    const float* __restrict__ nu_log, const float* __restrict__ th_log)
{
    int b = blockIdx.x / NCH, c = blockIdx.x % NCH;
    int n = threadIdx.x;
    float lr, li; lam_of(nu_log, th_log, n, lr, li);
    float xr = 0.f, xi = 0.f;
    size_t base = ((size_t)b * SEQ + (size_t)c * CHUNK) * NST + n;
    for (int t = 0; t < CHUNK; t++) {
        float br = g_bu_re[base + (size_t)t * NST];
        float bi = g_bu_im[base + (size_t)t * NST];
        float nxr = fmaf(lr, xr, fmaf(-li, xi, br));
        float nxi = fmaf(lr, xi, fmaf( li, xr, bi));
        xr = nxr; xi = nxi;
    }
    int p = (b * NCH + c) * NST + n;
    g_part_re[p] = xr;
    g_part_im[p] = xi;
}

// ---------------------------------------------------------------------------
// Scan phase 2: sequential prefix over the 32 chunks; overwrites partials
// with the state at chunk START. lam^CHUNK computed via 7 squarings.
// ---------------------------------------------------------------------------
__global__ __launch_bounds__(NST) void scan_phase2(
    const float* __restrict__ nu_log, const float* __restrict__ th_log)
{
    int b = blockIdx.x;
    int n = threadIdx.x;
    float lr, li; lam_of(nu_log, th_log, n, lr, li);
    float Lr = lr, Li = li;
    #pragma unroll
    for (int i = 0; i < 7; i++) {   // lam^(2^7) = lam^128 = lam^CHUNK
        float nr = Lr * Lr - Li * Li;
        float ni = 2.f * Lr * Li;
        Lr = nr; Li = ni;
    }
    float sr = 0.f, si = 0.f;
    for (int c = 0; c < NCH; c++) {
        int idx = (b * NCH + c) * NST + n;
        float pr = g_part_re[idx], pi = g_part_im[idx];
        g_part_re[idx] = sr;       // state at chunk start
        g_part_im[idx] = si;
        float nsr = fmaf(Lr, sr, fmaf(-Li, si, pr));
        float nsi = fmaf(Lr, si, fmaf( Li, sr, pi));
        sr = nsr; si = nsi;
    }
}

// ---------------------------------------------------------------------------
// Scan phase 3: replay each chunk from its start state, writing the SHIFTED
// state pre_t = x_{t-1} IN PLACE over Bu (read Bu_t before overwrite).
// ---------------------------------------------------------------------------
__global__ __launch_bounds__(NST) void scan_phase3(
    const float* __restrict__ nu_log, const float* __restrict__ th_log)
{
    int b = blockIdx.x / NCH, c = blockIdx.x % NCH;
    int n = threadIdx.x;
    float lr, li; lam_of(nu_log, th_log, n, lr, li);
    int p = (b * NCH + c) * NST + n;
    float xr = g_part_re[p], xi = g_part_im[p];
    size_t base = ((size_t)b * SEQ + (size_t)c * CHUNK) * NST + n;
    for (int t = 0; t < CHUNK; t++) {
        size_t off = base + (size_t)t * NST;
        float br = g_bu_re[off];
        float bi = g_bu_im[off];
        g_bu_re[off] = xr;          // pre_t = x_{t-1}
        g_bu_im[off] = xi;
        float nxr = fmaf(lr, xr, fmaf(-li, xi, br));
        float nxi = fmaf(lr, xi, fmaf( li, xr, bi));
        xr = nxr; xi = nxi;
    }
}

// ---------------------------------------------------------------------------
// GEMM 2 (fused epilogue):
// y[m,o] = sum_n pre_re[m,n]*C_re[o,n] - sum_n pre_im[m,n]*C_im[o,n]
//        + sum_h u[m,h]*D[o,h]
// Three accumulation passes through the same 64x64 tile machinery; the
// pass sign is folded into the W smem load.
// ---------------------------------------------------------------------------
__global__ __launch_bounds__(256) void gemm_y_kernel(
    const float* __restrict__ u, const float* __restrict__ Cre,
    const float* __restrict__ Cim, const float* __restrict__ Dm,
    float* __restrict__ y)
{
    __shared__ __align__(16) float As[32][68];
    __shared__ __align__(16) float Ws[32][68];
    const int m0 = blockIdx.x * 64;
    const int o0 = blockIdx.y * 64;
    const int tid = threadIdx.x;
    const int tx = tid & 15, ty = tid >> 4;

    float acc[4][4] = {};

    #pragma unroll 1
    for (int pass = 0; pass < 3; pass++) {
        const float* A = (pass == 0) ? g_bu_re : (pass == 1) ? g_bu_im : u;
        const float* W = (pass == 0) ? Cre     : (pass == 1) ? Cim     : Dm;
        const int    K = (pass == 2) ? HIN : NST;
        const float sgn = (pass == 1) ? -1.f : 1.f;
        for (int k0 = 0; k0 < K; k0 += 32) {
            #pragma unroll
            for (int i = 0; i < 8; i++) {
                int idx = tid + i * 256;
                int r = idx >> 5, kk = idx & 31;
                As[kk][r] = A[(size_t)(m0 + r) * K + (k0 + kk)];
                Ws[kk][r] = sgn * W[(size_t)(o0 + r) * K + (k0 + kk)];
            }
            __syncthreads();
            #pragma unroll
            for (int kk = 0; kk < 32; kk++) {
                float4 a4 = *reinterpret_cast<const float4*>(&As[kk][ty * 4]);
                float4 b4 = *reinterpret_cast<const float4*>(&Ws[kk][tx * 4]);
                float av[4] = {a4.x, a4.y, a4.z, a4.w};
                float bv[4] = {b4.x, b4.y, b4.z, b4.w};
                #pragma unroll
                for (int i = 0; i < 4; i++)
                    #pragma unroll
                    for (int j = 0; j < 4; j++)
                        acc[i][j] = fmaf(av[i], bv[j], acc[i][j]);
            }
            __syncthreads();
        }
    }

    #pragma unroll
    for (int i = 0; i < 4; i++) {
        int m = m0 + ty * 4 + i;
        float4 v;
        v.x = acc[i][0]; v.y = acc[i][1]; v.z = acc[i][2]; v.w = acc[i][3];
        *reinterpret_cast<float4*>(&y[(size_t)m * HOUT + o0 + tx * 4]) = v;
    }
}

extern "C" void kernel_launch(void* const* d_in, const int* in_sizes, int n_in,
                              void* d_out, int out_size) {
    const float* u         = (const float*)d_in[0];
    const float* nu_log    = (const float*)d_in[1];
    const float* theta_log = (const float*)d_in[2];
    const float* gamma_log = (const float*)d_in[3];
    const float* Bre       = (const float*)d_in[4];
    const float* Bim       = (const float*)d_in[5];
    const float* Cre       = (const float*)d_in[6];
    const float* Cim       = (const float*)d_in[7];
    const float* Dm        = (const float*)d_in[8];
    float* y = (float*)d_out;

    dim3 g1(MTOT / 64, NST / 64, 2);
    gemm_bu_kernel<<<g1, 256>>>(u, Bre, Bim, gamma_log);

    scan_phase1<<<BSZ * NCH, NST>>>(nu_log, theta_log);
    scan_phase2<<<BSZ, NST>>>(nu_log, theta_log);
    scan_phase3<<<BSZ * NCH, NST>>>(nu_log, theta_log);

    dim3 g2(MTOT / 64, HOUT / 64);
    gemm_y_kernel<<<g2, 256>>>(u, Cre, Cim, Dm, y);
}

// round 2
// speedup vs baseline: 1.9503x; 1.9503x over previous
#include <cuda_runtime.h>
#include <math.h>

#define BSZ   16
#define SEQ   4096
#define NST   256
#define HIN   128
#define HOUT  128
#define MTOT  (BSZ*SEQ)      // 65536
#define CHUNK 64
#define NCH   (SEQ/CHUNK)    // 64

// Scratch (allocation-free device globals). g_bu holds interleaved (re,im)
// and is overwritten in place by scan phase-3 with pre_t = x_{t-1}.
__device__ float2 g_bu[(size_t)MTOT*NST];
__device__ float2 g_part[BSZ*NCH*NST];

// ---------------- packed f32x2 helpers (sm_103a FFMA2) ----------------
__device__ __forceinline__ unsigned long long ffma2(unsigned long long a,
                                                    unsigned long long b,
                                                    unsigned long long c) {
    unsigned long long d;
    asm("fma.rn.f32x2 %0, %1, %2, %3;" : "=l"(d) : "l"(a), "l"(b), "l"(c));
    return d;
}
__device__ __forceinline__ unsigned long long f2dup(float a) {
    unsigned long long r;
    asm("mov.b64 %0, {%1, %1};" : "=l"(r) : "f"(a));
    return r;
}
__device__ __forceinline__ float2 f2unpack(unsigned long long v) {
    float2 r;
    asm("mov.b64 {%0, %1}, %2;" : "=f"(r.x), "=f"(r.y) : "l"(v));
    return r;
}

__device__ __forceinline__ void lam_of(const float* __restrict__ nu_log,
                                       const float* __restrict__ th_log,
                                       int n, float& lr, float& li) {
    float mod = expf(-expf(nu_log[n]));
    float th  = expf(th_log[n]);
    lr = mod * cosf(th);
    li = mod * sinf(th);
}

// ---------------------------------------------------------------------------
// GEMM 1 (fused re+im): Bu[m,n] = gamma[n] * (u[m,:] . B{re,im}[n,:])
// 64x64 tile, 256 threads, 4x4 microtile, accumulators packed (re,im) FFMA2.
// ---------------------------------------------------------------------------
__global__ __launch_bounds__(256) void gemm_bu_kernel(
    const float* __restrict__ u, const float* __restrict__ Bre,
    const float* __restrict__ Bim, const float* __restrict__ gamma_log)
{
    __shared__ __align__(16) float As[32][68];
    __shared__ __align__(16) float Ws[32][136];   // (re,im) interleaved, 64 states
    const int m0 = blockIdx.x * 64;
    const int n0 = blockIdx.y * 64;
    const int tid = threadIdx.x;
    const int tx = tid & 15, ty = tid >> 4;

    unsigned long long acc[4][4] = {};  // (re,im) per (i,j); 0 bits == (0.f,0.f)

    for (int k0 = 0; k0 < HIN; k0 += 32) {
        #pragma unroll
        for (int i = 0; i < 8; i++) {
            int idx = tid + i * 256;
            int r = idx >> 5, kk = idx & 31;
            As[kk][r]       = u  [(size_t)(m0 + r) * HIN + (k0 + kk)];
            Ws[kk][2*r]     = Bre[(size_t)(n0 + r) * HIN + (k0 + kk)];
            Ws[kk][2*r + 1] = Bim[(size_t)(n0 + r) * HIN + (k0 + kk)];
        }
        __syncthreads();
        #pragma unroll
        for (int kk = 0; kk < 32; kk++) {
            float4 a4 = *reinterpret_cast<const float4*>(&As[kk][ty * 4]);
            ulonglong2 p0 = *reinterpret_cast<const ulonglong2*>(&Ws[kk][tx * 8]);
            ulonglong2 p1 = *reinterpret_cast<const ulonglong2*>(&Ws[kk][tx * 8 + 4]);
            unsigned long long b[4] = {p0.x, p0.y, p1.x, p1.y};
            float av[4] = {a4.x, a4.y, a4.z, a4.w};
            #pragma unroll
            for (int i = 0; i < 4; i++) {
                unsigned long long a2 = f2dup(av[i]);
                #pragma unroll
                for (int j = 0; j < 4; j++)
                    acc[i][j] = ffma2(a2, b[j], acc[i][j]);
            }
        }
        __syncthreads();
    }

    float g[4];
    #pragma unroll
    for (int j = 0; j < 4; j++) g[j] = expf(gamma_log[n0 + tx * 4 + j]);
    #pragma unroll
    for (int i = 0; i < 4; i++) {
        int m = m0 + ty * 4 + i;
        float2 c0 = f2unpack(acc[i][0]), c1 = f2unpack(acc[i][1]);
        float2 c2 = f2unpack(acc[i][2]), c3 = f2unpack(acc[i][3]);
        float* outp = (float*)&g_bu[(size_t)m * NST + n0 + tx * 4];
        float4 v0 = {c0.x * g[0], c0.y * g[0], c1.x * g[1], c1.y * g[1]};
        float4 v1 = {c2.x * g[2], c2.y * g[2], c3.x * g[3], c3.y * g[3]};
        *reinterpret_cast<float4*>(outp)     = v0;
        *reinterpret_cast<float4*>(outp + 4) = v1;
    }
}

// ---------------------------------------------------------------------------
// Scan phase 1: per-chunk reduce with explicit MLP-16 load groups.
// Skips the last chunk of each batch (its partial is never consumed).
// ---------------------------------------------------------------------------
__global__ __launch_bounds__(NST) void scan_phase1(
    const float* __restrict__ nu_log, const float* __restrict__ th_log)
{
    int b = blockIdx.x / (NCH - 1), c = blockIdx.x % (NCH - 1);
    int n = threadIdx.x;
    float lr, li; lam_of(nu_log, th_log, n, lr, li);
    float xr = 0.f, xi = 0.f;
    size_t base = ((size_t)b * SEQ + (size_t)c * CHUNK) * NST + n;
    float2 buf[16];
    #pragma unroll 1
    for (int g = 0; g < CHUNK / 16; g++) {
        #pragma unroll
        for (int i = 0; i < 16; i++)
            buf[i] = g_bu[base + (size_t)(g * 16 + i) * NST];
        #pragma unroll
        for (int i = 0; i < 16; i++) {
            float br = buf[i].x, bi = buf[i].y;
            float nxr = fmaf(lr, xr, fmaf(-li, xi, br));
            float nxi = fmaf(lr, xi, fmaf( li, xr, bi));
            xr = nxr; xi = nxi;
        }
    }
    g_part[(b * NCH + c) * NST + n] = make_float2(xr, xi);
}

// ---------------------------------------------------------------------------
// Scan phase 2: sequential prefix over NCH chunks; overwrites partials
// with the state at chunk START. lam^CHUNK via 6 squarings (2^6 = 64).
// ---------------------------------------------------------------------------
__global__ __launch_bounds__(NST) void scan_phase2(
    const float* __restrict__ nu_log, const float* __restrict__ th_log)
{
    int b = blockIdx.x;
    int n = threadIdx.x;
    float lr, li; lam_of(nu_log, th_log, n, lr, li);
    float Lr = lr, Li = li;
    #pragma unroll
    for (int i = 0; i < 6; i++) {
        float nr = Lr * Lr - Li * Li;
        float ni = 2.f * Lr * Li;
        Lr = nr; Li = ni;
    }
    float sr = 0.f, si = 0.f;
    for (int c = 0; c < NCH; c++) {
        int idx = (b * NCH + c) * NST + n;
        float2 p = g_part[idx];
        g_part[idx] = make_float2(sr, si);   // state at chunk start
        float nsr = fmaf(Lr, sr, fmaf(-Li, si, p.x));
        float nsi = fmaf(Lr, si, fmaf( Li, sr, p.y));
        sr = nsr; si = nsi;
    }
}

// ---------------------------------------------------------------------------
// Scan phase 3: replay each chunk from its start state, writing pre_t =
// x_{t-1} IN PLACE over Bu. Explicit MLP-16 load groups before stores.
// ---------------------------------------------------------------------------
__global__ __launch_bounds__(NST) void scan_phase3(
    const float* __restrict__ nu_log, const float* __restrict__ th_log)
{
    int b = blockIdx.x / NCH, c = blockIdx.x % NCH;
    int n = threadIdx.x;
    float lr, li; lam_of(nu_log, th_log, n, lr, li);
    float2 s = g_part[(b * NCH + c) * NST + n];
    float xr = s.x, xi = s.y;
    size_t base = ((size_t)b * SEQ + (size_t)c * CHUNK) * NST + n;
    float2 buf[16];
    #pragma unroll 1
    for (int g = 0; g < CHUNK / 16; g++) {
        #pragma unroll
        for (int i = 0; i < 16; i++)
            buf[i] = g_bu[base + (size_t)(g * 16 + i) * NST];
        #pragma unroll
        for (int i = 0; i < 16; i++) {
            size_t off = base + (size_t)(g * 16 + i) * NST;
            g_bu[off] = make_float2(xr, xi);   // pre_t = x_{t-1}
            float br = buf[i].x, bi = buf[i].y;
            float nxr = fmaf(lr, xr, fmaf(-li, xi, br));
            float nxi = fmaf(lr, xi, fmaf( li, xr, bi));
            xr = nxr; xi = nxi;
        }
    }
}

// ---------------------------------------------------------------------------
// GEMM 2 (fused): y[m,o] = pre_re.C_re - pre_im.C_im + u.D
// 64x64 tile, 256 threads, 4x4 microtile, accumulators packed over o-pairs.
// ---------------------------------------------------------------------------
__global__ __launch_bounds__(256) void gemm_y_kernel(
    const float* __restrict__ u, const float* __restrict__ Cre,
    const float* __restrict__ Cim, const float* __restrict__ Dm,
    float* __restrict__ y)
{
    __shared__ __align__(16) float Ar[32][68];
    __shared__ __align__(16) float Ai[32][68];
    __shared__ __align__(16) float Wr[32][68];
    __shared__ __align__(16) float Wi[32][68];
    const int m0 = blockIdx.x * 64;
    const int o0 = blockIdx.y * 64;
    const int tid = threadIdx.x;
    const int tx = tid & 15, ty = tid >> 4;

    unsigned long long acc[4][2] = {};   // packed over (o, o+1) pairs

    // ---- complex pass: K = NST over pre (interleaved float2) ----
    #pragma unroll 1
    for (int k0 = 0; k0 < NST; k0 += 32) {
        #pragma unroll
        for (int i = 0; i < 8; i++) {
            int idx = tid + i * 256;
            int r = idx >> 5, kk = idx & 31;
            float2 v = g_bu[(size_t)(m0 + r) * NST + (k0 + kk)];
            Ar[kk][r] = v.x;
            Ai[kk][r] = v.y;
            Wr[kk][r] =  Cre[(size_t)(o0 + r) * NST + (k0 + kk)];
            Wi[kk][r] = -Cim[(size_t)(o0 + r) * NST + (k0 + kk)];
        }
        __syncthreads();
        #pragma unroll
        for (int kk = 0; kk < 32; kk++) {
            float4 ar4 = *reinterpret_cast<const float4*>(&Ar[kk][ty * 4]);
            float4 ai4 = *reinterpret_cast<const float4*>(&Ai[kk][ty * 4]);
            ulonglong2 wr = *reinterpret_cast<const ulonglong2*>(&Wr[kk][tx * 4]);
            ulonglong2 wi = *reinterpret_cast<const ulonglong2*>(&Wi[kk][tx * 4]);
            float avr[4] = {ar4.x, ar4.y, ar4.z, ar4.w};
            float avi[4] = {ai4.x, ai4.y, ai4.z, ai4.w};
            #pragma unroll
            for (int i = 0; i < 4; i++) {
                unsigned long long a2r = f2dup(avr[i]);
                unsigned long long a2i = f2dup(avi[i]);
                acc[i][0] = ffma2(a2r, wr.x, acc[i][0]);
                acc[i][0] = ffma2(a2i, wi.x, acc[i][0]);
                acc[i][1] = ffma2(a2r, wr.y, acc[i][1]);
                acc[i][1] = ffma2(a2i, wi.y, acc[i][1]);
            }
        }
        __syncthreads();
    }

    // ---- D pass: K = HIN over u ----
    #pragma unroll 1
    for (int k0 = 0; k0 < HIN; k0 += 32) {
        #pragma unroll
        for (int i = 0; i < 8; i++) {
            int idx = tid + i * 256;
            int r = idx >> 5, kk = idx & 31;
            Ar[kk][r] = u [(size_t)(m0 + r) * HIN + (k0 + kk)];
            Wr[kk][r] = Dm[(size_t)(o0 + r) * HIN + (k0 + kk)];
        }
        __syncthreads();
        #pragma unroll
        for (int kk = 0; kk < 32; kk++) {
            float4 a4 = *reinterpret_cast<const float4*>(&Ar[kk][ty * 4]);
            ulonglong2 w = *reinterpret_cast<const ulonglong2*>(&Wr[kk][tx * 4]);
            float av[4] = {a4.x, a4.y, a4.z, a4.w};
            #pragma unroll
            for (int i = 0; i < 4; i++) {
                unsigned long long a2 = f2dup(av[i]);
                acc[i][0] = ffma2(a2, w.x, acc[i][0]);
                acc[i][1] = ffma2(a2, w.y, acc[i][1]);
            }
        }
        __syncthreads();
    }

    #pragma unroll
    for (int i = 0; i < 4; i++) {
        int m = m0 + ty * 4 + i;
        float2 c0 = f2unpack(acc[i][0]);
        float2 c1 = f2unpack(acc[i][1]);
        float4 v = {c0.x, c0.y, c1.x, c1.y};
        *reinterpret_cast<float4*>(&y[(size_t)m * HOUT + o0 + tx * 4]) = v;
    }
}

extern "C" void kernel_launch(void* const* d_in, const int* in_sizes, int n_in,
                              void* d_out, int out_size) {
    const float* u         = (const float*)d_in[0];
    const float* nu_log    = (const float*)d_in[1];
    const float* theta_log = (const float*)d_in[2];
    const float* gamma_log = (const float*)d_in[3];
    const float* Bre       = (const float*)d_in[4];
    const float* Bim       = (const float*)d_in[5];
    const float* Cre       = (const float*)d_in[6];
    const float* Cim       = (const float*)d_in[7];
    const float* Dm        = (const float*)d_in[8];
    float* y = (float*)d_out;

    dim3 g1(MTOT / 64, NST / 64);
    gemm_bu_kernel<<<g1, 256>>>(u, Bre, Bim, gamma_log);

    scan_phase1<<<BSZ * (NCH - 1), NST>>>(nu_log, theta_log);
    scan_phase2<<<BSZ, NST>>>(nu_log, theta_log);
    scan_phase3<<<BSZ * NCH, NST>>>(nu_log, theta_log);

    dim3 g2(MTOT / 64, HOUT / 64);
    gemm_y_kernel<<<g2, 256>>>(u, Cre, Cim, Dm, y);
}

// round 4
// speedup vs baseline: 4.1701x; 2.1382x over previous
#include <cuda_runtime.h>
#include <math.h>
#include <stdint.h>

#define BSZ   16
#define SEQ   4096
#define NST   256
#define HIN   128
#define HOUT  128
#define MTOT  (BSZ*SEQ)      // 65536
#define CHUNK 64
#define NCH   (SEQ/CHUNK)    // 64

// Scratch (allocation-free device globals). g_bu holds interleaved (re,im)
// per state, flat fp32 layout [m][2n]=re, [m][2n+1]=im. Overwritten in place
// by scan phase-3 with pre_t = x_{t-1}.
__device__ float2 g_bu[(size_t)MTOT*NST];
__device__ float2 g_part[BSZ*NCH*NST];
// Pre-assembled weight matrices (built once per launch by prep_w):
//   g_wbu[n][k], n=2*state+parity: (parity?Bim:Bre)[state][k] * gamma[state]
//   g_wy [o][k], k<512: (k&1 ? -Cim : Cre)[o][k>>1]; k>=512: D[o][k-512]
__device__ float g_wbu[512 * HIN];
__device__ float g_wy[HOUT * 640];

// pack two fp32 -> bf16x2 (lo element in lower half)
__device__ __forceinline__ uint32_t packbf(float lo, float hi) {
    uint32_t r;
    asm("cvt.rn.bf16x2.f32 %0, %1, %2;" : "=r"(r) : "f"(hi), "f"(lo));
    return r;
}

#define MMA_BF16(d, a, b0, b1)                                        \
    asm("mma.sync.aligned.m16n8k16.row.col.f32.bf16.bf16.f32 "        \
        "{%0,%1,%2,%3},{%4,%5,%6,%7},{%8,%9},{%0,%1,%2,%3};"          \
        : "+f"(d[0]), "+f"(d[1]), "+f"(d[2]), "+f"(d[3])              \
        : "r"(a[0]), "r"(a[1]), "r"(a[2]), "r"(a[3]), "r"(b0), "r"(b1))

// smem layout (uint32 words): 4 planes (Ahi,Alo,Whi,Wlo) per buffer,
// each plane = 128 rows x 20 words (80B stride: conflict-free fragment loads).
#define PLW        2560
#define BUFW       (4*PLW)
#define SMEM_BYTES (2*BUFW*4)    // 81920

// ---------------------------------------------------------------------------
// prep: build g_wbu and g_wy once per launch (~150K elements).
// ---------------------------------------------------------------------------
__global__ __launch_bounds__(256) void prep_w(
    const float* __restrict__ Bre, const float* __restrict__ Bim,
    const float* __restrict__ gamma_log,
    const float* __restrict__ Cre, const float* __restrict__ Cim,
    const float* __restrict__ Dm)
{
    int i = blockIdx.x * 256 + threadIdx.x;
    if (i < 512 * HIN) {
        int n = i / HIN, k = i % HIN;
        const float* B = (n & 1) ? Bim : Bre;
        g_wbu[i] = B[(n >> 1) * HIN + k] * expf(gamma_log[n >> 1]);
    } else {
        int j = i - 512 * HIN;
        int o = j / 640, k = j % 640;
        float v;
        if (k < 512) {
            int n = k >> 1;
            v = (k & 1) ? -Cim[o * NST + n] : Cre[o * NST + n];
        } else {
            v = Dm[o * HIN + (k - 512)];
        }
        g_wy[j] = v;
    }
}

// ---------------------------------------------------------------------------
// Tensor-core GEMM via mma.sync bf16 + 3-product split:
//   C[128m, 128n] = A[128, K] x W[128n, K]^T, fp32 in/out.
// MODE 0: A = u (K=128); W = g_wbu tile ntile; out -> g_bu flat (stride 512)
// MODE 1: A = [g_bu flat | u] (K=640); W = g_wy; out -> y (stride 128)
// 8 warps, 32x64 warp tiles, double-buffered 32-wide K chunks.
// ---------------------------------------------------------------------------
template<int MODE>
__global__ __launch_bounds__(256) void mma_gemm(const float* __restrict__ u,
                                                float* __restrict__ y)
{
    extern __shared__ uint32_t sm[];
    const int tid = threadIdx.x, lane = tid & 31, wid = tid >> 5;
    const int warp_m = (wid & 3) * 32, warp_n = (wid >> 2) * 64;
    const int ntile = (MODE == 0) ? blockIdx.x : 0;
    const int m0 = blockIdx.y * 128;
    const int K  = (MODE == 0) ? HIN : 640;
    const int NC = K / 32;
    const float* W  = (MODE == 0) ? (g_wbu + (size_t)ntile * 128 * HIN) : g_wy;
    const int   WS  = (MODE == 0) ? HIN : 640;
    const float* bu = (const float*)g_bu;

    float acc[2][8][4];
    #pragma unroll
    for (int f = 0; f < 2; f++)
        #pragma unroll
        for (int j = 0; j < 8; j++)
            #pragma unroll
            for (int q = 0; q < 4; q++) acc[f][j][q] = 0.f;

    const int srow = tid >> 1;          // staging row 0..127
    const int sseg = (tid & 1) * 16;    // element offset within 32-chunk

    float4 a4[4], w4[4];

    auto ldg = [&](int kb) {
        const int kk = kb + sseg;
        const float* sa;
        if (MODE == 0) {
            sa = u + (size_t)(m0 + srow) * HIN + kk;
        } else {
            sa = (kk < 512) ? (bu + (size_t)(m0 + srow) * 512 + kk)
                            : (u + (size_t)(m0 + srow) * HIN + (kk - 512));
        }
        #pragma unroll
        for (int q = 0; q < 4; q++) a4[q] = ((const float4*)sa)[q];
        const float* sw = W + (size_t)srow * WS + kk;
        #pragma unroll
        for (int q = 0; q < 4; q++) w4[q] = ((const float4*)sw)[q];
    };

    auto sts = [&](int buf) {
        uint32_t* p = sm + buf * BUFW + srow * 20 + (sseg >> 1);
        uint32_t h[8], l[8];
        #pragma unroll
        for (int q = 0; q < 4; q++) {
            float e0 = a4[q].x, e1 = a4[q].y, e2 = a4[q].z, e3 = a4[q].w;
            uint32_t h0 = packbf(e0, e1), h1 = packbf(e2, e3);
            float f0 = __uint_as_float(h0 << 16), f1 = __uint_as_float(h0 & 0xffff0000u);
            float f2 = __uint_as_float(h1 << 16), f3 = __uint_as_float(h1 & 0xffff0000u);
            h[2*q] = h0; h[2*q+1] = h1;
            l[2*q]   = packbf(e0 - f0, e1 - f1);
            l[2*q+1] = packbf(e2 - f2, e3 - f3);
        }
        ((uint4*)p)[0]         = make_uint4(h[0], h[1], h[2], h[3]);
        ((uint4*)p)[1]         = make_uint4(h[4], h[5], h[6], h[7]);
        ((uint4*)(p + PLW))[0] = make_uint4(l[0], l[1], l[2], l[3]);
        ((uint4*)(p + PLW))[1] = make_uint4(l[4], l[5], l[6], l[7]);
        #pragma unroll
        for (int q = 0; q < 4; q++) {
            float e0 = w4[q].x, e1 = w4[q].y, e2 = w4[q].z, e3 = w4[q].w;
            uint32_t h0 = packbf(e0, e1), h1 = packbf(e2, e3);
            float f0 = __uint_as_float(h0 << 16), f1 = __uint_as_float(h0 & 0xffff0000u);
            float f2 = __uint_as_float(h1 << 16), f3 = __uint_as_float(h1 & 0xffff0000u);
            h[2*q] = h0; h[2*q+1] = h1;
            l[2*q]   = packbf(e0 - f0, e1 - f1);
            l[2*q+1] = packbf(e2 - f2, e3 - f3);
        }
        ((uint4*)(p + 2*PLW))[0] = make_uint4(h[0], h[1], h[2], h[3]);
        ((uint4*)(p + 2*PLW))[1] = make_uint4(h[4], h[5], h[6], h[7]);
        ((uint4*)(p + 3*PLW))[0] = make_uint4(l[0], l[1], l[2], l[3]);
        ((uint4*)(p + 3*PLW))[1] = make_uint4(l[4], l[5], l[6], l[7]);
    };

    auto comp = [&](int buf) {
        const uint32_t* base = sm + buf * BUFW;
        const int r0 = lane >> 2, kp = lane & 3;
        #pragma unroll
        for (int ks = 0; ks < 2; ks++) {
            const int kw = ks * 8 + kp;
            uint32_t ah[2][4], al[2][4];
            #pragma unroll
            for (int f = 0; f < 2; f++) {
                const uint32_t* pa = base + (warp_m + f * 16 + r0) * 20 + kw;
                ah[f][0] = pa[0];   ah[f][2] = pa[4];
                ah[f][1] = pa[160]; ah[f][3] = pa[164];     // +8 rows
                const uint32_t* pl = pa + PLW;
                al[f][0] = pl[0];   al[f][2] = pl[4];
                al[f][1] = pl[160]; al[f][3] = pl[164];
            }
            #pragma unroll
            for (int j = 0; j < 8; j++) {
                const uint32_t* pw = base + 2 * PLW + (warp_n + j * 8 + r0) * 20 + kw;
                uint32_t bh0 = pw[0],   bh1 = pw[4];
                uint32_t bl0 = pw[PLW], bl1 = pw[PLW + 4];
                #pragma unroll
                for (int f = 0; f < 2; f++) {
                    MMA_BF16(acc[f][j], ah[f], bh0, bh1);
                    MMA_BF16(acc[f][j], ah[f], bl0, bl1);
                    MMA_BF16(acc[f][j], al[f], bh0, bh1);
                }
            }
        }
    };

    ldg(0); sts(0); __syncthreads();
    #pragma unroll 1
    for (int c = 0; c < NC; c++) {
        if (c + 1 < NC) ldg((c + 1) * 32);
        comp(c & 1);
        if (c + 1 < NC) sts((c + 1) & 1);
        __syncthreads();
    }

    float* dst;
    int stride;
    if (MODE == 0) { dst = (float*)g_bu + (size_t)ntile * 128; stride = 512; }
    else           { dst = y;                                   stride = HOUT; }
    #pragma unroll
    for (int f = 0; f < 2; f++) {
        const int m = m0 + warp_m + f * 16 + (lane >> 2);
        #pragma unroll
        for (int j = 0; j < 8; j++) {
            const int n = warp_n + j * 8 + (lane & 3) * 2;
            *(float2*)(dst + (size_t)m * stride + n) =
                make_float2(acc[f][j][0], acc[f][j][1]);
            *(float2*)(dst + (size_t)(m + 8) * stride + n) =
                make_float2(acc[f][j][2], acc[f][j][3]);
        }
    }
}

// ============================== scan kernels ===============================
__device__ __forceinline__ void lam_of(const float* __restrict__ nu_log,
                                       const float* __restrict__ th_log,
                                       int n, float& lr, float& li) {
    float mod = expf(-expf(nu_log[n]));
    float th  = expf(th_log[n]);
    lr = mod * cosf(th);
    li = mod * sinf(th);
}

__global__ __launch_bounds__(NST) void scan_phase1(
    const float* __restrict__ nu_log, const float* __restrict__ th_log)
{
    int b = blockIdx.x / (NCH - 1), c = blockIdx.x % (NCH - 1);
    int n = threadIdx.x;
    float lr, li; lam_of(nu_log, th_log, n, lr, li);
    float xr = 0.f, xi = 0.f;
    size_t base = ((size_t)b * SEQ + (size_t)c * CHUNK) * NST + n;
    float2 buf[16];
    #pragma unroll 1
    for (int g = 0; g < CHUNK / 16; g++) {
        #pragma unroll
        for (int i = 0; i < 16; i++)
            buf[i] = g_bu[base + (size_t)(g * 16 + i) * NST];
        #pragma unroll
        for (int i = 0; i < 16; i++) {
            float br = buf[i].x, bi = buf[i].y;
            float nxr = fmaf(lr, xr, fmaf(-li, xi, br));
            float nxi = fmaf(lr, xi, fmaf( li, xr, bi));
            xr = nxr; xi = nxi;
        }
    }
    g_part[(b * NCH + c) * NST + n] = make_float2(xr, xi);
}

__global__ __launch_bounds__(NST) void scan_phase2(
    const float* __restrict__ nu_log, const float* __restrict__ th_log)
{
    int b = blockIdx.x;
    int n = threadIdx.x;
    float lr, li; lam_of(nu_log, th_log, n, lr, li);
    float Lr = lr, Li = li;
    #pragma unroll
    for (int i = 0; i < 6; i++) {    // lam^64 = lam^CHUNK
        float nr = Lr * Lr - Li * Li;
        float ni = 2.f * Lr * Li;
        Lr = nr; Li = ni;
    }
    float sr = 0.f, si = 0.f;
    for (int c = 0; c < NCH; c++) {
        int idx = (b * NCH + c) * NST + n;
        float2 p = g_part[idx];
        g_part[idx] = make_float2(sr, si);   // state at chunk start
        float nsr = fmaf(Lr, sr, fmaf(-Li, si, p.x));
        float nsi = fmaf(Lr, si, fmaf( Li, sr, p.y));
        sr = nsr; si = nsi;
    }
}

__global__ __launch_bounds__(NST) void scan_phase3(
    const float* __restrict__ nu_log, const float* __restrict__ th_log)
{
    int b = blockIdx.x / NCH, c = blockIdx.x % NCH;
    int n = threadIdx.x;
    float lr, li; lam_of(nu_log, th_log, n, lr, li);
    float2 s = g_part[(b * NCH + c) * NST + n];
    float xr = s.x, xi = s.y;
    size_t base = ((size_t)b * SEQ + (size_t)c * CHUNK) * NST + n;
    float2 buf[16];
    #pragma unroll 1
    for (int g = 0; g < CHUNK / 16; g++) {
        #pragma unroll
        for (int i = 0; i < 16; i++)
            buf[i] = g_bu[base + (size_t)(g * 16 + i) * NST];
        #pragma unroll
        for (int i = 0; i < 16; i++) {
            size_t off = base + (size_t)(g * 16 + i) * NST;
            g_bu[off] = make_float2(xr, xi);   // pre_t = x_{t-1}
            float br = buf[i].x, bi = buf[i].y;
            float nxr = fmaf(lr, xr, fmaf(-li, xi, br));
            float nxi = fmaf(lr, xi, fmaf( li, xr, bi));
            xr = nxr; xi = nxi;
        }
    }
}

// ================================ launch ===================================
extern "C" void kernel_launch(void* const* d_in, const int* in_sizes, int n_in,
                              void* d_out, int out_size) {
    const float* u         = (const float*)d_in[0];
    const float* nu_log    = (const float*)d_in[1];
    const float* theta_log = (const float*)d_in[2];
    const float* gamma_log = (const float*)d_in[3];
    const float* Bre       = (const float*)d_in[4];
    const float* Bim       = (const float*)d_in[5];
    const float* Cre       = (const float*)d_in[6];
    const float* Cim       = (const float*)d_in[7];
    const float* Dm        = (const float*)d_in[8];
    float* y = (float*)d_out;

    cudaFuncSetAttribute(mma_gemm<0>,
                         cudaFuncAttributeMaxDynamicSharedMemorySize, SMEM_BYTES);
    cudaFuncSetAttribute(mma_gemm<1>,
                         cudaFuncAttributeMaxDynamicSharedMemorySize, SMEM_BYTES);

    prep_w<<<(512 * HIN + HOUT * 640) / 256, 256>>>(Bre, Bim, gamma_log, Cre, Cim, Dm);

    // GEMM1: g_bu = gamma * (u @ [Bre|Bim]^T) (ntile fastest for u L2 reuse)
    dim3 gb(4, MTOT / 128);
    mma_gemm<0><<<gb, 256, SMEM_BYTES>>>(u, nullptr);

    scan_phase1<<<BSZ * (NCH - 1), NST>>>(nu_log, theta_log);
    scan_phase2<<<BSZ, NST>>>(nu_log, theta_log);
    scan_phase3<<<BSZ * NCH, NST>>>(nu_log, theta_log);

    // GEMM2: y = pre_re@Cre^T - pre_im@Cim^T + u@D^T  (K=640 concat)
    dim3 gy(1, MTOT / 128);
    mma_gemm<1><<<gy, 256, SMEM_BYTES>>>(u, y);
}